// round 16
// baseline (speedup 1.0000x reference)
#include <cuda_runtime.h>

#define H 51
#define BB 14            // real batches per CTA
#define NTHREADS 512
#define KHALF 26         // k's per half (pad 51 -> 52)
#define HOFF 432         // half-1 k-range float offset: 1728B ≡ 64 (mod 128)
#define HSTRIDE 864      // floats per h buffer parity: 3456B ≡ 0 (mod 128)
#define GROWS 462        // gbuf rows: 3 regions x 154
#define GPUP 8           // gbuf pitch (ull) = 64B
#define GR2 154
#define GR3 308
#define OFF_TABS 10848   // float offsets in smem
#define OFF_XBUF 11208
#define OFF_OACC 11224
#define OFF_RED  11256   // [2][13][16]
#define SMEM_FLOATS 11672

typedef unsigned long long ull;

#define FFMA2(d, a, b_) asm("fma.rn.f32x2 %0, %1, %2, %0;" : "+l"(d) : "l"(a), "l"(b_))
#define ADDF2(d, a)     asm("add.rn.f32x2 %0, %0, %1;"     : "+l"(d) : "l"(a))

__device__ __forceinline__ ull pack2(float lo, float hi) {
    ull r;
    asm("mov.b64 %0, {%1,%2};" : "=l"(r) : "f"(lo), "f"(hi));
    return r;
}
__device__ __forceinline__ float2 unpack2(ull v) {
    float lo, hi;
    asm("mov.b64 {%0,%1}, %2;" : "=f"(lo), "=f"(hi) : "l"(v));
    return make_float2(lo, hi);
}
__device__ __forceinline__ float sigf(float v)   { return __fdividef(1.0f, 1.0f + __expf(-v)); }
__device__ __forceinline__ float tanh_f(float v) { return 1.0f - __fdividef(2.0f, __expf(2.0f * v) + 1.0f); }
// h element float index of k-row start (rows padded to 16 floats; 16-float gap before half 1)
__device__ __forceinline__ int hidx(int k) { return k * 16 + (k >= KHALF ? 16 : 0); }

__global__ __launch_bounds__(NTHREADS, 1)
void gru2_kernel(const float* __restrict__ input,
                 const float* __restrict__ w_ih1, const float* __restrict__ w_hh1,
                 const float* __restrict__ b_ih1, const float* __restrict__ b_hh1,
                 const float* __restrict__ w_ih2, const float* __restrict__ w_hh2,
                 const float* __restrict__ b_ih2, const float* __restrict__ b_hh2,
                 const float* __restrict__ w_lin, const float* __restrict__ b_lin,
                 float* __restrict__ out, int T, int F, int B)
{
    extern __shared__ float sm[];
    float* hT1   = sm;                          // [2][864]
    float* hT2   = sm + 2 * HSTRIDE;            // [2][864]
    ull*   gbufU = (ull*)(sm + 4 * HSTRIDE);    // [462][8]
    const float2* g2 = (const float2*)gbufU;    // float2 pitch = 8
    float* tabs  = sm + OFF_TABS;
    float* xbuf  = sm + OFF_XBUF;               // [16] (14 real + 2 pad)
    float* oacc  = sm + OFF_OACC;               // [2][16]
    float* red   = sm + OFF_RED;                // [2][13][16]

    const int tid  = threadIdx.x;
    const int lane = tid & 31;
    const int gb0  = blockIdx.x * BB;
    const int TOT  = T + F;

    for (int j = tid; j < 4 * HSTRIDE; j += NTHREADS) sm[j] = 0.f;
    for (int j = tid; j < 16 + 32 + 416; j += NTHREADS) xbuf[j] = 0.f;
    if (tid < H) {
        tabs[tid]         = __ldg(&w_ih1[tid]);
        tabs[H + tid]     = __ldg(&w_ih1[H + tid]);
        tabs[2 * H + tid] = __ldg(&w_ih1[2 * H + tid]);
        tabs[3 * H + tid] = __ldg(&b_ih1[tid]);
        tabs[4 * H + tid] = __ldg(&b_ih1[H + tid]);
        tabs[5 * H + tid] = __ldg(&b_ih1[2 * H + tid]);
        tabs[6 * H + tid] = __ldg(&w_lin[tid]);
    }

    // ---- dot setup (R12 core: 231 row-pairs x k-split-2) ----
    const bool comp = (tid < 462);
    const int P    = comp ? (tid >> 1) : 0;
    const int half = tid & 1;
    const unsigned pmask = 0x3u << (tid & 30);
    const int region = P / 77;
    const int q      = P - region * 77;
    const int ra = 2 * q, rb = 2 * q + 1;
    const bool vB = (rb < 153);
    const float* wsrc = (region == 0) ? w_hh1 : ((region == 1) ? w_hh2 : w_ih2);
    const float* bsrc = (region == 0) ? b_hh1 : ((region == 1) ? b_hh2 : b_ih2);
    const int hsel = (region == 1);

    float wA[KHALF], wB[KHALF];
    #pragma unroll
    for (int j = 0; j < KHALF; ++j) {
        int k = half * KHALF + j;
        wA[j] = (comp && k < H) ? __ldg(&wsrc[ra * H + k]) : 0.f;
        wB[j] = (comp && vB && k < H) ? __ldg(&wsrc[rb * H + k]) : 0.f;
    }
    float bA  = comp ? __ldg(&bsrc[ra]) : 0.f;
    float bBv = (comp && vB) ? __ldg(&bsrc[rb]) : 0.f;
    const ull biasA = half ? 0ULL : pack2(bA, bA);
    const ull biasB = half ? 0ULL : pack2(bBv, bBv);
    const float blin = __ldg(&b_lin[0]);
    const int pxor = hsel ? 0 : 1;
    const float* hbase = hsel ? hT2 : hT1;
    const int hoff = half * HOFF;
    const int growA = region * 154 + ra;

    __syncthreads();

    for (int i = 0; i <= TOT; ++i) {
        const int par = i & 1;

        // ================= DOT STAGE (7 batch-pair accs) + helper warp 15 =================
        if (comp) {
            const float* hp = hbase + (par ^ pxor) * HSTRIDE + hoff;
            ull aA[7], aB[7];
            #pragma unroll
            for (int bp = 0; bp < 7; ++bp) { aA[bp] = biasA; aB[bp] = biasB; }
            #pragma unroll
            for (int k = 0; k < KHALF; ++k) {
                const ull wdA = pack2(wA[k], wA[k]);
                const ull wdB = pack2(wB[k], wB[k]);
                const float* rowp = hp + k * 16;
                const ulonglong2* qq = (const ulonglong2*)rowp;
                ulonglong2 q0 = qq[0], q1 = qq[1], q2 = qq[2];
                ull q3 = *(const ull*)(rowp + 12);
                FFMA2(aA[0], wdA, q0.x); FFMA2(aA[1], wdA, q0.y);
                FFMA2(aA[2], wdA, q1.x); FFMA2(aA[3], wdA, q1.y);
                FFMA2(aA[4], wdA, q2.x); FFMA2(aA[5], wdA, q2.y);
                FFMA2(aA[6], wdA, q3);
                FFMA2(aB[0], wdB, q0.x); FFMA2(aB[1], wdB, q0.y);
                FFMA2(aB[2], wdB, q1.x); FFMA2(aB[3], wdB, q1.y);
                FFMA2(aB[4], wdB, q2.x); FFMA2(aB[5], wdB, q2.y);
                FFMA2(aB[6], wdB, q3);
            }
            #pragma unroll
            for (int bp = 0; bp < 7; ++bp) {
                ull t;
                t = __shfl_xor_sync(pmask, aA[bp], 1); ADDF2(aA[bp], t);
                t = __shfl_xor_sync(pmask, aB[bp], 1); ADDF2(aB[bp], t);
            }
            if (!half) {
                ull* gA = gbufU + growA * GPUP;
                ull* gB = gbufU + (growA + 1) * GPUP;
                ((ulonglong2*)gA)[0] = make_ulonglong2(aA[0], aA[1]);
                ((ulonglong2*)gA)[1] = make_ulonglong2(aA[2], aA[3]);
                ((ulonglong2*)gA)[2] = make_ulonglong2(aA[4], aA[5]);
                gA[6] = aA[6];
                ((ulonglong2*)gB)[0] = make_ulonglong2(aB[0], aB[1]);
                ((ulonglong2*)gB)[1] = make_ulonglong2(aB[2], aB[3]);
                ((ulonglong2*)gB)[2] = make_ulonglong2(aB[4], aB[5]);
                gB[6] = aB[6];
            }
        } else if (tid >= 480) {
            int l = tid - 480;
            if (l < BB && gb0 + l < B) {
                if (i >= 2 && i <= T) {           // finalize o[i-2] from red scratch
                    const float* rr = red + (par ^ 1) * 208;
                    float s = 0.f;
                    #pragma unroll
                    for (int r = 0; r < 13; ++r) s += rr[r * 16 + l];
                    out[(size_t)(gb0 + l) * TOT + (i - 2)] = s + blin;
                }
                if (i < T) xbuf[l] = __ldg(&input[(size_t)(gb0 + l) * T + i]);
            }
            if (l < 16 && i >= T) oacc[par * 16 + l] = 0.f;
        }
        __syncthreads();

        // ================= POINTWISE STAGE =================
        float* h2c = hT2 + par * HSTRIDE;          // h2[i-2]
        float* h2n = hT2 + (par ^ 1) * HSTRIDE;    // h2[i-1]
        float* h1c = hT1 + (par ^ 1) * HSTRIDE;    // h1[i-1]
        float* h1n = hT1 + par * HSTRIDE;          // h1[i]

        if (i < T) {
            // ---- L2 pointwise + shfl-tree reduction: warps 0-12 ----
            if (tid < 416) {
                int u = tid >> 3, bp = tid & 7;
                float v0 = 0.f, v1 = 0.f;
                if (i > 0 && u < H && bp < 7) {
                    int hx = hidx(u) + 2 * bp;
                    float2 dir = g2[(GR3 + u) * GPUP + bp];
                    float2 diz = g2[(GR3 + 51 + u) * GPUP + bp];
                    float2 din = g2[(GR3 + 102 + u) * GPUP + bp];
                    float2 d2r = g2[(GR2 + u) * GPUP + bp];
                    float2 d2z = g2[(GR2 + 51 + u) * GPUP + bp];
                    float2 d2n = g2[(GR2 + 102 + u) * GPUP + bp];
                    float2 hold = *(const float2*)(h2c + hx);
                    float r0 = sigf(dir.x + d2r.x), r1 = sigf(dir.y + d2r.y);
                    float z0 = sigf(diz.x + d2z.x), z1 = sigf(diz.y + d2z.y);
                    float n0 = tanh_f(fmaf(r0, d2n.x, din.x));
                    float n1 = tanh_f(fmaf(r1, d2n.y, din.y));
                    float h0 = n0 + z0 * (hold.x - n0);
                    float h1 = n1 + z1 * (hold.y - n1);
                    *(float2*)(h2n + hx) = make_float2(h0, h1);
                    float wl = tabs[6 * H + u];
                    v0 = wl * h0; v1 = wl * h1;
                }
                ull pv = pack2(v0, v1), t;
                t = __shfl_xor_sync(0xFFFFFFFFu, pv, 8);  ADDF2(pv, t);
                t = __shfl_xor_sync(0xFFFFFFFFu, pv, 16); ADDF2(pv, t);
                if ((lane & 24) == 0)
                    *(float2*)(red + par * 208 + (tid >> 5) * 16 + 2 * (lane & 7)) = unpack2(pv);
            }
            // ---- L1 pointwise: threads 104..511 ----
            int jj = tid - 104;
            if (jj >= 0 && jj < 408) {
                int u = jj >> 3, bp = jj & 7;
                if (u < H && bp < 7) {
                    int hx = hidx(u) + 2 * bp;
                    float2 x2 = *(const float2*)(xbuf + 2 * bp);
                    float2 ar = g2[u * GPUP + bp];
                    float2 az = g2[(51 + u) * GPUP + bp];
                    float2 an = g2[(102 + u) * GPUP + bp];
                    float2 hold = *(const float2*)(h1c + hx);
                    float w1r = tabs[u], w1z = tabs[H + u], w1n = tabs[2 * H + u];
                    float c1r = tabs[3 * H + u], c1z = tabs[4 * H + u], c1n = tabs[5 * H + u];
                    float r0 = sigf(fmaf(x2.x, w1r, c1r) + ar.x);
                    float r1 = sigf(fmaf(x2.y, w1r, c1r) + ar.y);
                    float z0 = sigf(fmaf(x2.x, w1z, c1z) + az.x);
                    float z1 = sigf(fmaf(x2.y, w1z, c1z) + az.y);
                    float n0 = tanh_f(fmaf(x2.x, w1n, c1n) + r0 * an.x);
                    float n1 = tanh_f(fmaf(x2.y, w1n, c1n) + r1 * an.y);
                    float h0 = n0 + z0 * (hold.x - n0);
                    float h1 = n1 + z1 * (hold.y - n1);
                    *(float2*)(h1n + hx) = make_float2(h0, h1);
                }
            }
            __syncthreads();
        } else {
            // ---- future mode: L2 (+atomic o) -> sync -> out + L1 -> sync ----
            float* oa = oacc + par * 16;
            if (tid < 416) {
                int u = tid >> 3, bp = tid & 7;
                if (u < H && bp < 7) {
                    int hx = hidx(u) + 2 * bp;
                    float2 dir = g2[(GR3 + u) * GPUP + bp];
                    float2 diz = g2[(GR3 + 51 + u) * GPUP + bp];
                    float2 din = g2[(GR3 + 102 + u) * GPUP + bp];
                    float2 d2r = g2[(GR2 + u) * GPUP + bp];
                    float2 d2z = g2[(GR2 + 51 + u) * GPUP + bp];
                    float2 d2n = g2[(GR2 + 102 + u) * GPUP + bp];
                    float2 hold = *(const float2*)(h2c + hx);
                    float r0 = sigf(dir.x + d2r.x), r1 = sigf(dir.y + d2r.y);
                    float z0 = sigf(diz.x + d2z.x), z1 = sigf(diz.y + d2z.y);
                    float n0 = tanh_f(fmaf(r0, d2n.x, din.x));
                    float n1 = tanh_f(fmaf(r1, d2n.y, din.y));
                    float h0 = n0 + z0 * (hold.x - n0);
                    float h1 = n1 + z1 * (hold.y - n1);
                    *(float2*)(h2n + hx) = make_float2(h0, h1);
                    float wl = tabs[6 * H + u];
                    atomicAdd(&oa[2 * bp],     wl * h0);
                    atomicAdd(&oa[2 * bp + 1], wl * h1);
                }
            }
            __syncthreads();
            if (tid < BB && gb0 + tid < B)
                out[(size_t)(gb0 + tid) * TOT + (i - 1)] = oa[tid] + blin;
            int jj = tid - 104;
            if (jj >= 0 && jj < 408) {
                int u = jj >> 3, bp = jj & 7;
                if (u < H && bp < 7) {
                    int hx = hidx(u) + 2 * bp;
                    float2 x2 = *(const float2*)(oa + 2 * bp);
                    x2.x += blin; x2.y += blin;
                    float2 ar = g2[u * GPUP + bp];
                    float2 az = g2[(51 + u) * GPUP + bp];
                    float2 an = g2[(102 + u) * GPUP + bp];
                    float2 hold = *(const float2*)(h1c + hx);
                    float w1r = tabs[u], w1z = tabs[H + u], w1n = tabs[2 * H + u];
                    float c1r = tabs[3 * H + u], c1z = tabs[4 * H + u], c1n = tabs[5 * H + u];
                    float r0 = sigf(fmaf(x2.x, w1r, c1r) + ar.x);
                    float r1 = sigf(fmaf(x2.y, w1r, c1r) + ar.y);
                    float z0 = sigf(fmaf(x2.x, w1z, c1z) + az.x);
                    float z1 = sigf(fmaf(x2.y, w1z, c1z) + az.y);
                    float n0 = tanh_f(fmaf(x2.x, w1n, c1n) + r0 * an.x);
                    float n1 = tanh_f(fmaf(x2.y, w1n, c1n) + r1 * an.y);
                    float h0 = n0 + z0 * (hold.x - n0);
                    float h1 = n1 + z1 * (hold.y - n1);
                    *(float2*)(h1n + hx) = make_float2(h0, h1);
                }
            }
            __syncthreads();
        }
    }
}

extern "C" void kernel_launch(void* const* d_in, const int* in_sizes, int n_in,
                              void* d_out, int out_size) {
    const float* input = (const float*)d_in[0];
    const float* w_ih1 = (const float*)d_in[2];
    const float* w_hh1 = (const float*)d_in[3];
    const float* b_ih1 = (const float*)d_in[4];
    const float* b_hh1 = (const float*)d_in[5];
    const float* w_ih2 = (const float*)d_in[6];
    const float* w_hh2 = (const float*)d_in[7];
    const float* b_ih2 = (const float*)d_in[8];
    const float* b_hh2 = (const float*)d_in[9];
    const float* w_lin = (const float*)d_in[10];
    const float* b_lin = (const float*)d_in[11];

    const int B   = 2048;
    const int T   = in_sizes[0] / B;
    const int TOT = out_size / B;
    const int F   = TOT - T;
    const int grid = (B + BB - 1) / BB;   // 147

    size_t smem = (size_t)SMEM_FLOATS * sizeof(float);
    cudaFuncSetAttribute(gru2_kernel, cudaFuncAttributeMaxDynamicSharedMemorySize, (int)smem);

    gru2_kernel<<<grid, NTHREADS, smem>>>(
        input, w_ih1, w_hh1, b_ih1, b_hh1,
        w_ih2, w_hh2, b_ih2, b_hh2,
        w_lin, b_lin, (float*)d_out, T, F, B);
}